// round 3
// baseline (speedup 1.0000x reference)
#include <cuda_runtime.h>
#include <cstdint>

// APoT (8-bit, m=2) quantizer, eval forward:
//   apos = |alpha| + 1e-5
//   a    = clamp(RN(x / apos), -1, 1)
//   q(a) = nearest codebook level, tie -> smaller value
//   out  = q(a) * apos
//
// Codebook positive levels are exactly {B + off}: B = 2^-e (e in [1,15] plus 1.0),
// off in {0} U {2^-k : 2^-15 <= 2^-k <= B}; min positive level 2^-15.
// Nearest-with-tie == round the exact fraction f = m - B (Sterbenz) to the
// nearest allowed power of two, tie direction given by the sign bit s
// (positive: tie -> smaller magnitude; negative: tie -> larger magnitude).
//
//   um = bits(min(|a|, 1))                      (FMNMX, abs as src-mod)
//   uB = um & 0x7F800000                        (binade base)
//   Bf = (uB >= 2^-15) ? B : 0                  (low binades round m vs {0,2^-15})
//   f  = m - Bf                                 (exact FADD)
//   t  = bits(f) + 0x3FFFFF + s                 (pow2 rounding: mantissa
//                                                >= 0x400001-s carries into exp)
//   off = (t <= 0x37BFFFFF) ? 0                 (f below/at the 2^-16 tie -> 0)
//       : max(t & 0xFF800000, bits(2^-15))      (offset floor 2^-15)
//   v  = Bf + off (exact);  out = copysign(v) * apos
//
// Division: Markstein with r = __frcp_rn(apos): q0 = x*r; e = fma(-apos,q0,x);
// a = fma(e,r,q0) is the correctly rounded quotient == __fdiv_rn == reference.

__device__ __forceinline__ float apot_quant(float x, float apos, float r) {
    float q0 = x * r;
    float e  = fmaf(-apos, q0, x);
    float a  = fmaf(e, r, q0);

    unsigned ua = __float_as_uint(a);
    unsigned s  = ua >> 31;
    float    m  = fminf(fabsf(a), 1.0f);          // single FMNMX
    unsigned um = __float_as_uint(m);
    unsigned uB = um & 0x7F800000u;

    const unsigned C15 = 0x38000000u;             // bits(2^-15)
    float Bf = (uB >= C15) ? __uint_as_float(uB) : 0.0f;

    float    f  = m - Bf;                          // exact
    unsigned t  = __float_as_uint(f) + 0x3FFFFFu + s;
    unsigned rb = umax(t & 0xFF800000u, C15);
    unsigned off = (t <= 0x37BFFFFFu) ? 0u : rb;

    float v = Bf + __uint_as_float(off);           // exact codebook level
    unsigned uv = __float_as_uint(v) | (ua & 0x80000000u);
    return __uint_as_float(uv) * apos;
}

__device__ __forceinline__ float4 quant4(float4 v, float apos, float r) {
    float4 o;
    o.x = apot_quant(v.x, apos, r);
    o.y = apot_quant(v.y, apos, r);
    o.z = apot_quant(v.z, apos, r);
    o.w = apot_quant(v.w, apos, r);
    return o;
}

// Fast path: n divisible by 256*4*4 = 4096 elements per block.
// 4 float4 per thread at compile-time offsets -> LDG.128 [R+imm], front-batched.
__global__ void __launch_bounds__(256)
apot_fast(const float4* __restrict__ x4,
          const float* __restrict__ alpha,
          float4* __restrict__ o4)
{
    float apos = fabsf(__ldg(alpha)) + 1e-5f;
    float r    = __frcp_rn(apos);

    int base = blockIdx.x * (256 * 4) + threadIdx.x;

    float4 v0 = __ldcs(x4 + base);
    float4 v1 = __ldcs(x4 + base + 256);
    float4 v2 = __ldcs(x4 + base + 512);
    float4 v3 = __ldcs(x4 + base + 768);

    __stcs(o4 + base,       quant4(v0, apos, r));
    __stcs(o4 + base + 256, quant4(v1, apos, r));
    __stcs(o4 + base + 512, quant4(v2, apos, r));
    __stcs(o4 + base + 768, quant4(v3, apos, r));
}

// Generic fallback: grid-stride, bounds-checked, handles any n.
__global__ void __launch_bounds__(256)
apot_generic(const float* __restrict__ x,
             const float* __restrict__ alpha,
             float* __restrict__ out,
             int n)
{
    float apos = fabsf(__ldg(alpha)) + 1e-5f;
    float r    = __frcp_rn(apos);

    int n4      = n >> 2;
    int gtid    = blockIdx.x * blockDim.x + threadIdx.x;
    int gstride = gridDim.x * blockDim.x;

    const float4* __restrict__ x4 = reinterpret_cast<const float4*>(x);
    float4* __restrict__ o4       = reinterpret_cast<float4*>(out);

    for (int i = gtid; i < n4; i += gstride)
        __stcs(&o4[i], quant4(__ldcs(&x4[i]), apos, r));
    for (int i = (n4 << 2) + gtid; i < n; i += gstride)
        out[i] = apot_quant(x[i], apos, r);
}

extern "C" void kernel_launch(void* const* d_in, const int* in_sizes, int n_in,
                              void* d_out, int out_size)
{
    const float* x     = (const float*)d_in[0];   // x: fp32
    const float* alpha = (const float*)d_in[1];   // alpha: fp32 scalar
    // d_in[2] = codebook — deterministic APoT set, reproduced arithmetically.
    float* out = (float*)d_out;

    int n = in_sizes[0];
    const int ELEMS_PER_BLOCK = 256 * 4 * 4;      // 4096

    if (n > 0 && (n % ELEMS_PER_BLOCK) == 0) {
        int blocks = n / ELEMS_PER_BLOCK;         // 8192 for 4096x8192
        apot_fast<<<blocks, 256>>>((const float4*)x, alpha, (float4*)out);
    } else {
        int n4 = n >> 2;
        int blocks = (n4 + 256 * 2 - 1) / (256 * 2);
        if (blocks < 1) blocks = 1;
        apot_generic<<<blocks, 256>>>(x, alpha, out, n);
    }
}